// round 4
// baseline (speedup 1.0000x reference)
#include <cuda_runtime.h>
#include <cstdint>

// ---------------- problem constants ----------------
constexpr int B    = 8;
constexpr int C    = 5;
constexpr int NN   = 512;   // nodes
constexpr int FIN  = 768;
constexpr int H    = 4;
constexpr int DHID = 128;
constexpr int DOUT = 64;
constexpr int HD   = H * DHID;   // 512
constexpr int HD2  = H * DOUT;   // 256
constexpr int BC   = B * C;      // 40

// ---------------- scratch (device globals; no allocation allowed) ----------------
__device__ __align__(256) float g_feat[(size_t)BC * NN * HD];   // 41.9 MB
__device__ __align__(256) float g_h   [(size_t)BC * NN * HD];   // 41.9 MB
__device__ __align__(256) float g_out2[(size_t)BC * NN * HD2];  // 21.0 MB
__device__ __align__(256) float g_el  [BC * H * NN];
__device__ __align__(256) float g_er  [BC * H * NN];

// XOR swizzle for 16x128 smem planes: conflict-free mma fragment reads
#define SWZ(k, x) (((k) << 7) + ((x) ^ (((k) & 3) << 3)))

__device__ __forceinline__ uint32_t f2tf32(float f) {
    uint32_t u;
    asm("cvt.rna.tf32.f32 %0, %1;" : "=r"(u) : "f"(f));
    return u;
}

__device__ __forceinline__ void mma_tf32(float* d, const uint32_t* a, const uint32_t* b) {
    asm volatile(
        "mma.sync.aligned.m16n8k8.row.col.f32.tf32.tf32.f32 "
        "{%0,%1,%2,%3}, {%4,%5,%6,%7}, {%8,%9}, {%0,%1,%2,%3};\n"
        : "+f"(d[0]), "+f"(d[1]), "+f"(d[2]), "+f"(d[3])
        : "r"(a[0]), "r"(a[1]), "r"(a[2]), "r"(a[3]), "r"(b[0]), "r"(b[1]));
}

// ---------------- tf32 tensor-core GEMM, 3-stage pipelined -------------
// C[bc] (512 x Nn) = A[bc](512 x K) @ W[c](K x Nn). 128x128 tile, BK=16,
// 8 warps as 2(m) x 4(n); per warp 64m x 32n = 4x4 m16n8k8 tiles.
// Dynamic smem ring: 3 stages x [Ahi|Alo|Bhi|Blo] x 2048 u32 = 96KB.
__global__ __launch_bounds__(256) void gemm_tc(
    const float* __restrict__ A, const float* __restrict__ W,
    float* __restrict__ Co, int K, int Nn, size_t aSB, size_t aSC) {
    extern __shared__ uint32_t sm[];   // 3 * 8192 u32

    int bc = blockIdx.z;
    int b  = bc / C, c = bc % C;
    const float* Ab = A + (size_t)b * aSB + (size_t)c * aSC;
    const float* Wc = W + (size_t)c * K * Nn;
    float*       Cb = Co + (size_t)bc * NN * Nn;

    int m0 = blockIdx.y * 128, n0 = blockIdx.x * 128;
    int tid  = threadIdx.x;
    int lane = tid & 31, warp = tid >> 5;
    int wm = warp & 1, wn = warp >> 1;       // 2 x 4 warp grid
    int gr = lane >> 2, tg = lane & 3;       // groupID, threadInGroup

    // per-thread global-load coordinates (fixed)
    int ar0 = tid >> 2,        akq = (tid & 3) * 4;        // A: l=0
    int ar1 = (tid + 256) >> 2;                            // A: l=1 (same kq)
    int bk0 = tid >> 5,        bnq = (tid & 31) * 4;       // B: l=0
    int bk1 = (tid + 256) >> 5;                            // B: l=1 (same nq)

    float4 ra[2], rb[2];

    auto load_tile = [&](int t) {
        const float* Abt = Ab + (size_t)m0 * K + t * 16 + akq;
        ra[0] = *(const float4*)(Abt + (size_t)ar0 * K);
        ra[1] = *(const float4*)(Abt + (size_t)ar1 * K);
        const float* Wct = Wc + (size_t)(t * 16) * Nn + n0 + bnq;
        rb[0] = *(const float4*)(Wct + (size_t)bk0 * Nn);
        rb[1] = *(const float4*)(Wct + (size_t)bk1 * Nn);
    };

    auto store_stage = [&](int st) {
        uint32_t* Ahi = sm + st * 8192;
        uint32_t* Alo = Ahi + 2048;
        uint32_t* Bhi = Alo + 2048;
        uint32_t* Blo = Bhi + 2048;
#pragma unroll
        for (int l = 0; l < 2; l++) {
            int row = l ? ar1 : ar0;
            float vv[4] = {ra[l].x, ra[l].y, ra[l].z, ra[l].w};
#pragma unroll
            for (int i = 0; i < 4; i++) {
                int k = akq + i;
                uint32_t hi = f2tf32(vv[i]);
                Ahi[SWZ(k, row)] = hi;
                Alo[SWZ(k, row)] = f2tf32(vv[i] - __uint_as_float(hi));
            }
            int krow = l ? bk1 : bk0;
            float ww[4] = {rb[l].x, rb[l].y, rb[l].z, rb[l].w};
#pragma unroll
            for (int i = 0; i < 4; i++) {
                int n = bnq + i;
                uint32_t hi = f2tf32(ww[i]);
                Bhi[SWZ(krow, n)] = hi;
                Blo[SWZ(krow, n)] = f2tf32(ww[i] - __uint_as_float(hi));
            }
        }
    };

    float acc[4][4][4] = {};                 // [mt][nt][reg]

    auto compute_stage = [&](int st) {
        const uint32_t* Ahi = sm + st * 8192;
        const uint32_t* Alo = Ahi + 2048;
        const uint32_t* Bhi = Alo + 2048;
        const uint32_t* Blo = Bhi + 2048;
#pragma unroll
        for (int ks = 0; ks < 16; ks += 8) {
            int kA = ks + tg;
            uint32_t ah[4][4], al[4][4], bh[4][2], bl[4][2];
#pragma unroll
            for (int mt = 0; mt < 4; mt++) {
                int m = wm * 64 + mt * 16 + gr;
                ah[mt][0] = Ahi[SWZ(kA, m)];
                ah[mt][1] = Ahi[SWZ(kA, m + 8)];
                ah[mt][2] = Ahi[SWZ(kA + 4, m)];
                ah[mt][3] = Ahi[SWZ(kA + 4, m + 8)];
                al[mt][0] = Alo[SWZ(kA, m)];
                al[mt][1] = Alo[SWZ(kA, m + 8)];
                al[mt][2] = Alo[SWZ(kA + 4, m)];
                al[mt][3] = Alo[SWZ(kA + 4, m + 8)];
            }
#pragma unroll
            for (int nt = 0; nt < 4; nt++) {
                int n = wn * 32 + nt * 8 + gr;
                bh[nt][0] = Bhi[SWZ(kA, n)];
                bh[nt][1] = Bhi[SWZ(kA + 4, n)];
                bl[nt][0] = Blo[SWZ(kA, n)];
                bl[nt][1] = Blo[SWZ(kA + 4, n)];
            }
#pragma unroll
            for (int mt = 0; mt < 4; mt++)
#pragma unroll
                for (int nt = 0; nt < 4; nt++) {
                    mma_tf32(acc[mt][nt], ah[mt], bh[nt]);
                    mma_tf32(acc[mt][nt], al[mt], bh[nt]);
                    mma_tf32(acc[mt][nt], ah[mt], bl[nt]);
                }
        }
    };

    // ---- 3-stage pipeline ----
    int T = K / 16;
    load_tile(0);
    store_stage(0);
    load_tile(1);
    __syncthreads();

    for (int i = 0; i < T; i++) {
        if (i + 1 < T) store_stage((i + 1) % 3);   // regs(tile i+1) -> smem
        if (i + 2 < T) load_tile(i + 2);           // LDG issued early
        compute_stage(i % 3);
        __syncthreads();
    }

    // ---- epilogue ----
#pragma unroll
    for (int mt = 0; mt < 4; mt++) {
#pragma unroll
        for (int nt = 0; nt < 4; nt++) {
            int row = m0 + wm * 64 + mt * 16 + gr;
            int col = n0 + wn * 32 + nt * 8 + tg * 2;
            *(float2*)(Cb + (size_t)row * Nn + col) =
                make_float2(acc[mt][nt][0], acc[mt][nt][1]);
            *(float2*)(Cb + (size_t)(row + 8) * Nn + col) =
                make_float2(acc[mt][nt][2], acc[mt][nt][3]);
        }
    }
}

// ---------------- el/er: per-head dot products of feat rows with a_l / a_r ----------------
__global__ void elr_kernel(const float* __restrict__ feat,
                           const float* __restrict__ al,
                           const float* __restrict__ ar,
                           float* __restrict__ el, float* __restrict__ er, int D) {
    int bcn = blockIdx.x;            // bc*NN + i
    int bc = bcn / NN, i = bcn % NN;
    int c = bc % C;
    int h = threadIdx.x >> 5, lane = threadIdx.x & 31;

    const float* f   = feat + (size_t)bcn * (H * D) + h * D;
    const float* alh = al + (size_t)(c * H + h) * D;
    const float* arh = ar + (size_t)(c * H + h) * D;

    float sl = 0.f, sr = 0.f;
    for (int d = lane; d < D; d += 32) {
        float v = f[d];
        sl = fmaf(v, alh[d], sl);
        sr = fmaf(v, arh[d], sr);
    }
#pragma unroll
    for (int o = 16; o; o >>= 1) {
        sl += __shfl_down_sync(0xffffffffu, sl, o);
        sr += __shfl_down_sync(0xffffffffu, sr, o);
    }
    if (lane == 0) {
        el[((size_t)bc * H + h) * NN + i] = sl;
        er[((size_t)bc * H + h) * NN + i] = sr;
    }
}

// ---------------- fused softmax + aggregation (unchanged) ----------------
template <int D, bool RELU>
__global__ void agg_kernel(const float* __restrict__ adj,
                           const float* __restrict__ feat,
                           const float* __restrict__ el,
                           const float* __restrict__ er,
                           const float* __restrict__ bias,
                           float* __restrict__ out) {
    constexpr int TN = D / 16;            // 8 (D=128) or 4 (D=64)
    __shared__ float el_s[NN];
    __shared__ float er_s[128], m_s[128], sc_s[128];
    __shared__ float p_s[16][128];
    __shared__ float f_s[16][D];
    __shared__ float red[8];
    __shared__ float s_red[2][128];

    int bc = blockIdx.z, h = blockIdx.y;
    int c = bc % C;
    int j0 = blockIdx.x * 128;
    int tid = threadIdx.x;
    int lane = tid & 31, warp = tid >> 5;

    const float* adj_bc = adj + (size_t)bc * NN * NN;
    const float* elh = el + (size_t)(bc * H + h) * NN;
    const float* erh = er + (size_t)(bc * H + h) * NN;

    float e0 = elh[tid], e1 = elh[tid + 256];
    el_s[tid] = e0; el_s[tid + 256] = e1;
    if (tid < 128) er_s[tid] = erh[j0 + tid];

    float v = fmaxf(e0, e1);
#pragma unroll
    for (int o = 16; o; o >>= 1) v = fmaxf(v, __shfl_xor_sync(0xffffffffu, v, o));
    if (lane == 0) red[warp] = v;
    __syncthreads();
    if (tid == 0) {
        float m = red[0];
#pragma unroll
        for (int w = 1; w < 8; w++) m = fmaxf(m, red[w]);
        red[0] = m;
    }
    __syncthreads();
    if (tid < 128) {
        float e = red[0] + er_s[tid];
        m_s[tid] = e > 0.f ? e : 0.2f * e;
    }
    __syncthreads();

    int tx = tid % 16, ty = tid / 16;
    int jj0 = ty * 8, dd0 = tx * TN;
    int pj = tid & 127, pi0 = tid >> 7;

    float acc[8][TN] = {};
    float s_priv = 0.f;

    for (int ib = 0; ib < NN; ib += 16) {
#pragma unroll
        for (int l = 0; l < (16 * D / 4) / 256; l++) {
            int s = tid + l * 256;
            int r = s / (D / 4), cq = s % (D / 4);
            float4 fv4 = *(const float4*)(feat + ((size_t)bc * NN + ib + r) * (H * D) + h * D + cq * 4);
            *(float4*)&f_s[r][cq * 4] = fv4;
        }
#pragma unroll
        for (int q = 0; q < 8; q++) {
            int i = pi0 + q * 2;
            float a = adj_bc[(size_t)(ib + i) * NN + j0 + pj];
            float p = 0.f;
            if (a > 0.f) {
                float e = el_s[ib + i] + er_s[pj];
                e = e > 0.f ? e : 0.2f * e;
                p = __expf(e - m_s[pj]);
                s_priv += p;
            }
            p_s[i][pj] = p;
        }
        __syncthreads();
#pragma unroll
        for (int i = 0; i < 16; i++) {
            float pv[8], fv[TN];
            *(float4*)&pv[0] = *(const float4*)&p_s[i][jj0];
            *(float4*)&pv[4] = *(const float4*)&p_s[i][jj0 + 4];
#pragma unroll
            for (int q = 0; q < TN / 4; q++)
                *(float4*)&fv[q * 4] = *(const float4*)&f_s[i][dd0 + q * 4];
#pragma unroll
            for (int jj = 0; jj < 8; jj++)
#pragma unroll
                for (int dd = 0; dd < TN; dd++) acc[jj][dd] = fmaf(pv[jj], fv[dd], acc[jj][dd]);
        }
        __syncthreads();
    }

    s_red[pi0][pj] = s_priv;
    __syncthreads();
    if (tid < 128) sc_s[tid] = 1.0f / fmaxf(s_red[0][tid] + s_red[1][tid], 1e-9f);
    __syncthreads();

    const float* bh = bias + (size_t)c * (H * D) + h * D;
#pragma unroll
    for (int jj = 0; jj < 8; jj++) {
        int j = j0 + jj0 + jj;
        float sc = sc_s[jj0 + jj];
        float vals[TN];
#pragma unroll
        for (int dd = 0; dd < TN; dd++) {
            float o = acc[jj][dd] * sc + bh[dd0 + dd];
            if (RELU) o = fmaxf(o, 0.f);
            vals[dd] = o;
        }
#pragma unroll
        for (int q = 0; q < TN / 4; q++)
            *(float4*)(out + ((size_t)bc * NN + j) * (H * D) + h * D + dd0 + q * 4) =
                *(float4*)&vals[q * 4];
    }
}

// ---------------- head-mean + channel concat ----------------
__global__ void mean_kernel(const float* __restrict__ in2, float* __restrict__ out) {
    int idx = blockIdx.x * 256 + threadIdx.x;
    if (idx >= B * NN * C * DOUT) return;
    int d = idx % DOUT;
    int c = (idx / DOUT) % C;
    int n = (idx / (DOUT * C)) % NN;
    int b = idx / (DOUT * C * NN);
    const float* p = in2 + ((size_t)(b * C + c) * NN + n) * HD2 + d;
    out[idx] = 0.25f * (p[0] + p[DOUT] + p[2 * DOUT] + p[3 * DOUT]);
}

// ---------------- launch ----------------
extern "C" void kernel_launch(void* const* d_in, const int* in_sizes, int n_in,
                              void* d_out, int out_size) {
    const float* x   = (const float*)d_in[0];
    const float* adj = (const float*)d_in[1];
    const float* W0  = (const float*)d_in[2];
    const float* al0 = (const float*)d_in[3];
    const float* ar0 = (const float*)d_in[4];
    const float* b0  = (const float*)d_in[5];
    const float* W1  = (const float*)d_in[6];
    const float* al1 = (const float*)d_in[7];
    const float* ar1 = (const float*)d_in[8];
    const float* b1  = (const float*)d_in[9];
    const float* W2  = (const float*)d_in[10];
    const float* al2 = (const float*)d_in[11];
    const float* ar2 = (const float*)d_in[12];
    const float* b2  = (const float*)d_in[13];
    float* out = (float*)d_out;

    float *feat, *hbuf, *el, *er, *out2;
    cudaGetSymbolAddress((void**)&feat, g_feat);
    cudaGetSymbolAddress((void**)&hbuf, g_h);
    cudaGetSymbolAddress((void**)&el,   g_el);
    cudaGetSymbolAddress((void**)&er,   g_er);
    cudaGetSymbolAddress((void**)&out2, g_out2);

    dim3 t256(256);
    constexpr int GEMM_SMEM = 3 * 8192 * 4;   // 96KB
    static int attr_set = 0;
    if (!attr_set) {
        cudaFuncSetAttribute(gemm_tc, cudaFuncAttributeMaxDynamicSharedMemorySize, GEMM_SMEM);
        attr_set = 1;
    }

    // ---- layer 0 (input: x[:,0], shared across channels) ----
    gemm_tc<<<dim3(HD / 128, NN / 128, BC), t256, GEMM_SMEM>>>(x, W0, feat, FIN, HD,
                                                               (size_t)C * NN * FIN, 0);
    elr_kernel<<<BC * NN, 128>>>(feat, al0, ar0, el, er, DHID);
    agg_kernel<DHID, true><<<dim3(NN / 128, H, BC), t256>>>(adj, feat, el, er, b0, hbuf);

    // ---- layer 1 ----
    gemm_tc<<<dim3(HD / 128, NN / 128, BC), t256, GEMM_SMEM>>>(hbuf, W1, feat, HD, HD,
                                                               (size_t)C * NN * HD, (size_t)NN * HD);
    elr_kernel<<<BC * NN, 128>>>(feat, al1, ar1, el, er, DHID);
    agg_kernel<DHID, true><<<dim3(NN / 128, H, BC), t256>>>(adj, feat, el, er, b1, hbuf);

    // ---- layer 2 ----
    gemm_tc<<<dim3(HD2 / 128, NN / 128, BC), t256, GEMM_SMEM>>>(hbuf, W2, feat, HD, HD2,
                                                                (size_t)C * NN * HD, (size_t)NN * HD);
    elr_kernel<<<BC * NN, 128>>>(feat, al2, ar2, el, er, DOUT);
    agg_kernel<DOUT, false><<<dim3(NN / 128, H, BC), t256>>>(adj, feat, el, er, b2, out2);

    // ---- head mean + concat ----
    mean_kernel<<<(B * NN * C * DOUT + 255) / 256, t256>>>(out2, out);
}

// round 5
// speedup vs baseline: 1.7864x; 1.7864x over previous
#include <cuda_runtime.h>
#include <cstdint>

// ---------------- problem constants ----------------
constexpr int B    = 8;
constexpr int C    = 5;
constexpr int NN   = 512;   // nodes
constexpr int FIN  = 768;
constexpr int H    = 4;
constexpr int DHID = 128;
constexpr int DOUT = 64;
constexpr int HD   = H * DHID;   // 512
constexpr int HD2  = H * DOUT;   // 256
constexpr int BC   = B * C;      // 40

// ---------------- scratch (device globals; no allocation allowed) ----------------
__device__ __align__(256) float g_feat[(size_t)BC * NN * HD];
__device__ __align__(256) float g_h   [(size_t)BC * NN * HD];
__device__ __align__(256) float g_out2[(size_t)BC * NN * HD2];
__device__ __align__(256) float g_el  [BC * H * NN];
__device__ __align__(256) float g_er  [BC * H * NN];

// ---------------- gemm smem geometry (raw f32 staging, padded pitches) ----------------
constexpr int AP = 20;                 // A pitch (floats): banks (m*20+k)%32 conflict-free
constexpr int BP = 136;                // B pitch (floats): banks (k*136+n)%32 conflict-free
constexpr int A_STG = 128 * AP;        // 2560 floats
constexpr int B_STG = 16 * BP;         // 2176 floats
constexpr int STG   = A_STG + B_STG;   // 4736 floats = 18944 B
constexpr int GEMM_SMEM = 3 * STG * 4; // 56832 B

__device__ __forceinline__ uint32_t f2tf32(float f) {
    uint32_t u;
    asm("cvt.rna.tf32.f32 %0, %1;" : "=r"(u) : "f"(f));
    return u;
}

__device__ __forceinline__ void mma_tf32(float* d, const uint32_t* a, const uint32_t* b) {
    asm volatile(
        "mma.sync.aligned.m16n8k8.row.col.f32.tf32.tf32.f32 "
        "{%0,%1,%2,%3}, {%4,%5,%6,%7}, {%8,%9}, {%0,%1,%2,%3};\n"
        : "+f"(d[0]), "+f"(d[1]), "+f"(d[2]), "+f"(d[3])
        : "r"(a[0]), "r"(a[1]), "r"(a[2]), "r"(a[3]), "r"(b[0]), "r"(b[1]));
}

__device__ __forceinline__ void cp16(uint32_t smem_dst, const float* gsrc) {
    asm volatile("cp.async.ca.shared.global [%0], [%1], 16;\n"
                 :: "r"(smem_dst), "l"(gsrc));
}

// ---------------- tf32 tensor-core GEMM (split-at-load, cp.async 3-stage) ----------
// C[bc](512 x Nn) = A[bc](512 x K) @ W[c](K x Nn). 128x128 tile, BK=16,
// 8 warps as 2(m) x 4(n); per warp 64m x 32n = 4x4 m16n8k8 tiles, tf32 3-MMA split.
__global__ __launch_bounds__(256) void gemm_tc(
    const float* __restrict__ A, const float* __restrict__ W,
    float* __restrict__ Co, int K, int Nn, size_t aSB, size_t aSC) {
    extern __shared__ float sm[];   // 3 stages x [A(128x16,p20) | B(16x128,p136)]

    int bc = blockIdx.z;
    int b  = bc / C, c = bc % C;
    const float* Ab = A + (size_t)b * aSB + (size_t)c * aSC;
    const float* Wc = W + (size_t)c * K * Nn;
    float*       Cb = Co + (size_t)bc * NN * Nn;

    int m0 = blockIdx.y * 128, n0 = blockIdx.x * 128;
    int tid  = threadIdx.x;
    int lane = tid & 31, warp = tid >> 5;
    int wm = warp & 1, wn = warp >> 1;
    int gr = lane >> 2, tg = lane & 3;

    uint32_t smem_base = (uint32_t)__cvta_generic_to_shared(sm);

    // cp.async slot coordinates (2 A-chunks + 2 B-chunks per thread per stage)
    int am0 = tid >> 2,          akq = (tid & 3) * 4;
    int am1 = (tid + 256) >> 2;
    int bk0 = tid >> 5,          bnq = (tid & 31) * 4;
    int bk1 = (tid + 256) >> 5;

    auto issue_stage = [&](int st, int t) {
        uint32_t aB = smem_base + (st * STG) * 4;
        uint32_t bB = smem_base + (st * STG + A_STG) * 4;
        const float* Abt = Ab + (size_t)m0 * K + t * 16;
        cp16(aB + (am0 * AP + akq) * 4, Abt + (size_t)am0 * K + akq);
        cp16(aB + (am1 * AP + akq) * 4, Abt + (size_t)am1 * K + akq);
        const float* Wct = Wc + (size_t)(t * 16) * Nn + n0;
        cp16(bB + (bk0 * BP + bnq) * 4, Wct + (size_t)bk0 * Nn + bnq);
        cp16(bB + (bk1 * BP + bnq) * 4, Wct + (size_t)bk1 * Nn + bnq);
    };

    float acc[4][4][4] = {};

    auto compute_stage = [&](int st) {
        const float* As = sm + st * STG;          // [m][k] pitch AP
        const float* Bs = As + A_STG;             // [k][n] pitch BP
#pragma unroll
        for (int ks = 0; ks < 16; ks += 8) {
            int kA = ks + tg;
            uint32_t ah[4][4], al[4][4], bh[4][2], bl[4][2];
#pragma unroll
            for (int mt = 0; mt < 4; mt++) {
                int m = wm * 64 + mt * 16 + gr;
                float v0 = As[m * AP + kA];
                float v1 = As[(m + 8) * AP + kA];
                float v2 = As[m * AP + kA + 4];
                float v3 = As[(m + 8) * AP + kA + 4];
                ah[mt][0] = f2tf32(v0); al[mt][0] = f2tf32(v0 - __uint_as_float(ah[mt][0]));
                ah[mt][1] = f2tf32(v1); al[mt][1] = f2tf32(v1 - __uint_as_float(ah[mt][1]));
                ah[mt][2] = f2tf32(v2); al[mt][2] = f2tf32(v2 - __uint_as_float(ah[mt][2]));
                ah[mt][3] = f2tf32(v3); al[mt][3] = f2tf32(v3 - __uint_as_float(ah[mt][3]));
            }
#pragma unroll
            for (int nt = 0; nt < 4; nt++) {
                int n = wn * 32 + nt * 8 + gr;
                float w0 = Bs[kA * BP + n];
                float w1 = Bs[(kA + 4) * BP + n];
                bh[nt][0] = f2tf32(w0); bl[nt][0] = f2tf32(w0 - __uint_as_float(bh[nt][0]));
                bh[nt][1] = f2tf32(w1); bl[nt][1] = f2tf32(w1 - __uint_as_float(bh[nt][1]));
            }
#pragma unroll
            for (int mt = 0; mt < 4; mt++)
#pragma unroll
                for (int nt = 0; nt < 4; nt++) {
                    mma_tf32(acc[mt][nt], ah[mt], bh[nt]);
                    mma_tf32(acc[mt][nt], al[mt], bh[nt]);
                    mma_tf32(acc[mt][nt], ah[mt], bl[nt]);
                }
        }
    };

    int T = K / 16;
    issue_stage(0, 0);
    asm volatile("cp.async.commit_group;\n" ::);
    issue_stage(1, 1);
    asm volatile("cp.async.commit_group;\n" ::);

    for (int i = 0; i < T; i++) {
        asm volatile("cp.async.wait_group 1;\n" ::);
        __syncthreads();
        if (i + 2 < T) issue_stage((i + 2) % 3, i + 2);
        asm volatile("cp.async.commit_group;\n" ::);   // empty groups keep count uniform
        compute_stage(i % 3);
    }

#pragma unroll
    for (int mt = 0; mt < 4; mt++) {
#pragma unroll
        for (int nt = 0; nt < 4; nt++) {
            int row = m0 + wm * 64 + mt * 16 + gr;
            int col = n0 + wn * 32 + nt * 8 + tg * 2;
            *(float2*)(Cb + (size_t)row * Nn + col) =
                make_float2(acc[mt][nt][0], acc[mt][nt][1]);
            *(float2*)(Cb + (size_t)(row + 8) * Nn + col) =
                make_float2(acc[mt][nt][2], acc[mt][nt][3]);
        }
    }
}

// ---------------- el/er: per-head dot products of feat rows with a_l / a_r ----------------
__global__ void elr_kernel(const float* __restrict__ feat,
                           const float* __restrict__ al,
                           const float* __restrict__ ar,
                           float* __restrict__ el, float* __restrict__ er, int D) {
    int bcn = blockIdx.x;
    int bc = bcn / NN, i = bcn % NN;
    int c = bc % C;
    int h = threadIdx.x >> 5, lane = threadIdx.x & 31;

    const float* f   = feat + (size_t)bcn * (H * D) + h * D;
    const float* alh = al + (size_t)(c * H + h) * D;
    const float* arh = ar + (size_t)(c * H + h) * D;

    float sl = 0.f, sr = 0.f;
    for (int d = lane; d < D; d += 32) {
        float v = f[d];
        sl = fmaf(v, alh[d], sl);
        sr = fmaf(v, arh[d], sr);
    }
#pragma unroll
    for (int o = 16; o; o >>= 1) {
        sl += __shfl_down_sync(0xffffffffu, sl, o);
        sr += __shfl_down_sync(0xffffffffu, sr, o);
    }
    if (lane == 0) {
        el[((size_t)bc * H + h) * NN + i] = sl;
        er[((size_t)bc * H + h) * NN + i] = sr;
    }
}

// ---------------- fused softmax + aggregation (unchanged from R2) ----------------
template <int D, bool RELU>
__global__ void agg_kernel(const float* __restrict__ adj,
                           const float* __restrict__ feat,
                           const float* __restrict__ el,
                           const float* __restrict__ er,
                           const float* __restrict__ bias,
                           float* __restrict__ out) {
    constexpr int TN = D / 16;
    __shared__ float el_s[NN];
    __shared__ float er_s[128], m_s[128], sc_s[128];
    __shared__ float p_s[16][128];
    __shared__ float f_s[16][D];
    __shared__ float red[8];
    __shared__ float s_red[2][128];

    int bc = blockIdx.z, h = blockIdx.y;
    int c = bc % C;
    int j0 = blockIdx.x * 128;
    int tid = threadIdx.x;
    int lane = tid & 31, warp = tid >> 5;

    const float* adj_bc = adj + (size_t)bc * NN * NN;
    const float* elh = el + (size_t)(bc * H + h) * NN;
    const float* erh = er + (size_t)(bc * H + h) * NN;

    float e0 = elh[tid], e1 = elh[tid + 256];
    el_s[tid] = e0; el_s[tid + 256] = e1;
    if (tid < 128) er_s[tid] = erh[j0 + tid];

    float v = fmaxf(e0, e1);
#pragma unroll
    for (int o = 16; o; o >>= 1) v = fmaxf(v, __shfl_xor_sync(0xffffffffu, v, o));
    if (lane == 0) red[warp] = v;
    __syncthreads();
    if (tid == 0) {
        float m = red[0];
#pragma unroll
        for (int w = 1; w < 8; w++) m = fmaxf(m, red[w]);
        red[0] = m;
    }
    __syncthreads();
    if (tid < 128) {
        float e = red[0] + er_s[tid];
        m_s[tid] = e > 0.f ? e : 0.2f * e;
    }
    __syncthreads();

    int tx = tid % 16, ty = tid / 16;
    int jj0 = ty * 8, dd0 = tx * TN;
    int pj = tid & 127, pi0 = tid >> 7;

    float acc[8][TN] = {};
    float s_priv = 0.f;

    for (int ib = 0; ib < NN; ib += 16) {
#pragma unroll
        for (int l = 0; l < (16 * D / 4) / 256; l++) {
            int s = tid + l * 256;
            int r = s / (D / 4), cq = s % (D / 4);
            float4 fv4 = *(const float4*)(feat + ((size_t)bc * NN + ib + r) * (H * D) + h * D + cq * 4);
            *(float4*)&f_s[r][cq * 4] = fv4;
        }
#pragma unroll
        for (int q = 0; q < 8; q++) {
            int i = pi0 + q * 2;
            float a = adj_bc[(size_t)(ib + i) * NN + j0 + pj];
            float p = 0.f;
            if (a > 0.f) {
                float e = el_s[ib + i] + er_s[pj];
                e = e > 0.f ? e : 0.2f * e;
                p = __expf(e - m_s[pj]);
                s_priv += p;
            }
            p_s[i][pj] = p;
        }
        __syncthreads();
#pragma unroll
        for (int i = 0; i < 16; i++) {
            float pv[8], fv[TN];
            *(float4*)&pv[0] = *(const float4*)&p_s[i][jj0];
            *(float4*)&pv[4] = *(const float4*)&p_s[i][jj0 + 4];
#pragma unroll
            for (int q = 0; q < TN / 4; q++)
                *(float4*)&fv[q * 4] = *(const float4*)&f_s[i][dd0 + q * 4];
#pragma unroll
            for (int jj = 0; jj < 8; jj++)
#pragma unroll
                for (int dd = 0; dd < TN; dd++) acc[jj][dd] = fmaf(pv[jj], fv[dd], acc[jj][dd]);
        }
        __syncthreads();
    }

    s_red[pi0][pj] = s_priv;
    __syncthreads();
    if (tid < 128) sc_s[tid] = 1.0f / fmaxf(s_red[0][tid] + s_red[1][tid], 1e-9f);
    __syncthreads();

    const float* bh = bias + (size_t)c * (H * D) + h * D;
#pragma unroll
    for (int jj = 0; jj < 8; jj++) {
        int j = j0 + jj0 + jj;
        float sc = sc_s[jj0 + jj];
        float vals[TN];
#pragma unroll
        for (int dd = 0; dd < TN; dd++) {
            float o = acc[jj][dd] * sc + bh[dd0 + dd];
            if (RELU) o = fmaxf(o, 0.f);
            vals[dd] = o;
        }
#pragma unroll
        for (int q = 0; q < TN / 4; q++)
            *(float4*)(out + ((size_t)bc * NN + j) * (H * D) + h * D + dd0 + q * 4) =
                *(float4*)&vals[q * 4];
    }
}

// ---------------- head-mean + channel concat ----------------
__global__ void mean_kernel(const float* __restrict__ in2, float* __restrict__ out) {
    int idx = blockIdx.x * 256 + threadIdx.x;
    if (idx >= B * NN * C * DOUT) return;
    int d = idx % DOUT;
    int c = (idx / DOUT) % C;
    int n = (idx / (DOUT * C)) % NN;
    int b = idx / (DOUT * C * NN);
    const float* p = in2 + ((size_t)(b * C + c) * NN + n) * HD2 + d;
    out[idx] = 0.25f * (p[0] + p[DOUT] + p[2 * DOUT] + p[3 * DOUT]);
}

// ---------------- launch ----------------
extern "C" void kernel_launch(void* const* d_in, const int* in_sizes, int n_in,
                              void* d_out, int out_size) {
    const float* x   = (const float*)d_in[0];
    const float* adj = (const float*)d_in[1];
    const float* W0  = (const float*)d_in[2];
    const float* al0 = (const float*)d_in[3];
    const float* ar0 = (const float*)d_in[4];
    const float* b0  = (const float*)d_in[5];
    const float* W1  = (const float*)d_in[6];
    const float* al1 = (const float*)d_in[7];
    const float* ar1 = (const float*)d_in[8];
    const float* b1  = (const float*)d_in[9];
    const float* W2  = (const float*)d_in[10];
    const float* al2 = (const float*)d_in[11];
    const float* ar2 = (const float*)d_in[12];
    const float* b2  = (const float*)d_in[13];
    float* out = (float*)d_out;

    float *feat, *hbuf, *el, *er, *out2;
    cudaGetSymbolAddress((void**)&feat, g_feat);
    cudaGetSymbolAddress((void**)&hbuf, g_h);
    cudaGetSymbolAddress((void**)&el,   g_el);
    cudaGetSymbolAddress((void**)&er,   g_er);
    cudaGetSymbolAddress((void**)&out2, g_out2);

    dim3 t256(256);
    static int attr_set = 0;
    if (!attr_set) {
        cudaFuncSetAttribute(gemm_tc, cudaFuncAttributeMaxDynamicSharedMemorySize, GEMM_SMEM);
        attr_set = 1;
    }

    // ---- layer 0 ----
    gemm_tc<<<dim3(HD / 128, NN / 128, BC), t256, GEMM_SMEM>>>(x, W0, feat, FIN, HD,
                                                               (size_t)C * NN * FIN, 0);
    elr_kernel<<<BC * NN, 128>>>(feat, al0, ar0, el, er, DHID);
    agg_kernel<DHID, true><<<dim3(NN / 128, H, BC), t256>>>(adj, feat, el, er, b0, hbuf);

    // ---- layer 1 ----
    gemm_tc<<<dim3(HD / 128, NN / 128, BC), t256, GEMM_SMEM>>>(hbuf, W1, feat, HD, HD,
                                                               (size_t)C * NN * HD, (size_t)NN * HD);
    elr_kernel<<<BC * NN, 128>>>(feat, al1, ar1, el, er, DHID);
    agg_kernel<DHID, true><<<dim3(NN / 128, H, BC), t256>>>(adj, feat, el, er, b1, hbuf);

    // ---- layer 2 ----
    gemm_tc<<<dim3(HD2 / 128, NN / 128, BC), t256, GEMM_SMEM>>>(hbuf, W2, feat, HD, HD2,
                                                                (size_t)C * NN * HD, (size_t)NN * HD);
    elr_kernel<<<BC * NN, 128>>>(feat, al2, ar2, el, er, DOUT);
    agg_kernel<DOUT, false><<<dim3(NN / 128, H, BC), t256>>>(adj, feat, el, er, b2, out2);

    // ---- head mean + concat ----
    mean_kernel<<<(B * NN * C * DOUT + 255) / 256, t256>>>(out2, out);
}